// round 8
// baseline (speedup 1.0000x reference)
#include <cuda_runtime.h>
#include <cuda_fp16.h>
#include <math.h>
#include <stdint.h>

#define SEQ   256
#define NB    32
#define REC   16
#define EMB   32
#define VOCAB 32000
#define ROWS  (SEQ*NB)        /* 8192 */

#define TPB   256              /* threads per block */
#define CPB   1024             /* cols per block (4/thread) */
#define RPB   64               /* rows per block */
#define NCH   32               /* 32*1024 = 32768 >= 32000 */
#define NRT   (ROWS/RPB)       /* 128 row tiles */

__device__ float g_ih[ROWS*REC];
__device__ float g_hidden[ROWS*REC];
__device__ float g_part[ROWS*NCH];
__device__ float g_lse[ROWS];

/* ---------------- kernel 1: i_h = emb[idx] @ U^T + b1 ---------------- */
__global__ void k_ih(const int* __restrict__ inp, const float* __restrict__ emb,
                     const float* __restrict__ U, const float* __restrict__ b1)
{
    int gid = blockIdx.x*blockDim.x + threadIdx.x;
    if (gid >= ROWS*REC) return;
    int row = gid >> 4;
    int r   = gid & 15;
    int idx = inp[row];
    const float4* e4 = (const float4*)(emb + (size_t)idx*EMB);
    const float4* u4 = (const float4*)(U + r*EMB);
    float acc = b1[r];
    #pragma unroll
    for (int q = 0; q < 8; q++) {
        float4 e = e4[q], u = u4[q];
        acc += e.x*u.x + e.y*u.y + e.z*u.z + e.w*u.w;
    }
    g_ih[gid] = acc;
}

/* ---------------- kernel 2: sequential recurrence (1 warp / batch) ---- */
__global__ void k_rnn(const float* __restrict__ W, const float* __restrict__ b2,
                      const float* __restrict__ h0)
{
    int b = blockIdx.x;
    int r = threadIdx.x;
    __shared__ __align__(16) float ihs[SEQ*REC];   /* 16 KB */
    __shared__ float hs[REC];

    for (int s = r; s < SEQ; s += 32) {
        const float4* src = (const float4*)(g_ih + (size_t)(s*NB + b)*REC);
        float4* dst = (float4*)(ihs + s*REC);
        dst[0]=src[0]; dst[1]=src[1]; dst[2]=src[2]; dst[3]=src[3];
    }
    float wrow[REC]; float bias = 0.f;
    if (r < REC) {
        hs[r] = h0[r];
        #pragma unroll
        for (int k = 0; k < REC; k++) wrow[k] = W[r*REC + k];
        bias = b2[r];
    }
    __syncwarp();
    for (int s = 0; s < SEQ; s++) {
        float hn = 0.f;
        if (r < REC) {
            int row = s*NB + b;
            g_hidden[row*REC + r] = hs[r];          /* pre-update h */
            float acc = ihs[s*REC + r] + bias;
            #pragma unroll
            for (int k = 0; k < REC; k++) acc += wrow[k]*hs[k];
            hn = tanhf(acc);
        }
        __syncwarp();
        if (r < REC) hs[r] = hn;
        __syncwarp();
    }
}

/* ---------------- vocab pass via HFMA2 --------------------------------
   WRITE=0: per-row sum-of-exp partials.  WRITE=1: out = logit - lse.
   Block: 256 thr, 64 rows x 1024 cols. Thread owns 4 adjacent cols:
   v01[k] = (V[c0][k], V[c0+1][k]) half2, v23 likewise. h duplicated
   (h,h) half2 in shared. Per row: 4 LDS.128 + 32 HFMA2.
   Accumulate fp16 in two k-halves, combine in fp32.                     */
template<int WRITE>
__global__ void __launch_bounds__(TPB)
k_vocab(const float* __restrict__ V, float* __restrict__ out)
{
    __shared__ __align__(16) __half2 hs2[RPB*REC];   /* 4 KB: dup half2 */
    __shared__ float red[RPB*8];                     /* 2 KB */
    __shared__ float ls[RPB];
    int tid = threadIdx.x, wid = tid >> 5, lane = tid & 31;
    int rowBase = blockIdx.y * RPB;
    int c0 = blockIdx.x * CPB + tid*4;

    for (int i = tid; i < RPB*REC; i += TPB) {
        float h = g_hidden[(size_t)(rowBase + (i >> 4))*REC + (i & 15)];
        hs2[i] = __half2half2(__float2half_rn(h));
    }
    if (WRITE && tid < RPB) ls[tid] = g_lse[rowBase + tid];
    __syncthreads();

    bool valid = (c0 < VOCAB);
    __half2 v01[REC], v23[REC];
    if (valid) {
        const float4* p0 = (const float4*)(V + (size_t)c0*REC);
        const float4* p1 = (const float4*)(V + (size_t)(c0+1)*REC);
        const float4* p2 = (const float4*)(V + (size_t)(c0+2)*REC);
        const float4* p3 = (const float4*)(V + (size_t)(c0+3)*REC);
        #pragma unroll
        for (int q = 0; q < 4; q++) {
            float4 a = p0[q], b = p1[q], c = p2[q], d = p3[q];
            v01[q*4+0] = __floats2half2_rn(a.x, b.x);
            v01[q*4+1] = __floats2half2_rn(a.y, b.y);
            v01[q*4+2] = __floats2half2_rn(a.z, b.z);
            v01[q*4+3] = __floats2half2_rn(a.w, b.w);
            v23[q*4+0] = __floats2half2_rn(c.x, d.x);
            v23[q*4+1] = __floats2half2_rn(c.y, d.y);
            v23[q*4+2] = __floats2half2_rn(c.z, d.z);
            v23[q*4+3] = __floats2half2_rn(c.w, d.w);
        }
    } else {
        #pragma unroll
        for (int k = 0; k < REC; k++) {
            v01[k] = __half2half2(__float2half_rn(0.f));
            v23[k] = v01[k];
        }
    }

    const __half2 hz = __half2half2(__float2half_rn(0.f));

    #pragma unroll 2
    for (int rr = 0; rr < RPB; rr++) {
        const __half2* hp = hs2 + rr*REC;
        __half2 a01 = hz, b01 = hz, a23 = hz, b23 = hz;
        #pragma unroll
        for (int k = 0; k < 8; k++) {
            __half2 hh = hp[k];
            a01 = __hfma2(hh, v01[k], a01);
            a23 = __hfma2(hh, v23[k], a23);
        }
        #pragma unroll
        for (int k = 8; k < REC; k++) {
            __half2 hh = hp[k];
            b01 = __hfma2(hh, v01[k], b01);
            b23 = __hfma2(hh, v23[k], b23);
        }
        float2 fa01 = __half22float2(a01), fb01 = __half22float2(b01);
        float2 fa23 = __half22float2(a23), fb23 = __half22float2(b23);
        float d0 = fa01.x + fb01.x, d1 = fa01.y + fb01.y;
        float d2 = fa23.x + fb23.x, d3 = fa23.y + fb23.y;

        if (WRITE) {
            if (valid) {
                float l = ls[rr];
                float4 o = make_float4(d0-l, d1-l, d2-l, d3-l);
                *(float4*)(out + (size_t)(rowBase+rr)*VOCAB + c0) = o;
            }
        } else {
            float s = valid ? (__expf(d0)+__expf(d1)) + (__expf(d2)+__expf(d3))
                            : 0.f;
            #pragma unroll
            for (int off = 16; off; off >>= 1)
                s += __shfl_xor_sync(0xffffffffu, s, off);
            if (lane == 0) red[rr*8 + wid] = s;
        }
    }

    if (!WRITE) {
        __syncthreads();
        for (int rr = tid; rr < RPB; rr += TPB) {
            float t = 0.f;
            #pragma unroll
            for (int j = 0; j < 8; j++) t += red[rr*8 + j];
            g_part[(size_t)(rowBase + rr)*NCH + blockIdx.x] = t;
        }
    }
}

/* ---------------- lse[row] = log(sum of partials) -------------------- */
__global__ void k_lse()
{
    int row = blockIdx.x*blockDim.x + threadIdx.x;
    if (row >= ROWS) return;
    const float4* p = (const float4*)(g_part + (size_t)row*NCH);
    float s = 0.f;
    #pragma unroll
    for (int i = 0; i < NCH/4; i++) {
        float4 v = p[i];
        s += (v.x + v.y) + (v.z + v.w);
    }
    g_lse[row] = logf(s);
}

extern "C" void kernel_launch(void* const* d_in, const int* in_sizes, int n_in,
                              void* d_out, int out_size)
{
    const int*   inp = (const int*)d_in[0];
    const float* emb = (const float*)d_in[1];
    const float* U   = (const float*)d_in[2];
    const float* W   = (const float*)d_in[3];
    const float* V   = (const float*)d_in[4];
    const float* b1  = (const float*)d_in[5];
    const float* b2  = (const float*)d_in[6];
    const float* h0  = (const float*)d_in[7];
    float* out = (float*)d_out;

    k_ih<<<(ROWS*REC + 255)/256, 256>>>(inp, emb, U, b1);
    k_rnn<<<NB, 32>>>(W, b2, h0);
    k_vocab<0><<<dim3(NCH, NRT), TPB>>>(V, nullptr);
    k_lse<<<(ROWS + 255)/256, 256>>>();
    k_vocab<1><<<dim3(NCH, NRT), TPB>>>(V, out);
}

// round 10
// speedup vs baseline: 1.4853x; 1.4853x over previous
#include <cuda_runtime.h>
#include <math.h>
#include <stdint.h>

#define SEQ   256
#define NB    32
#define REC   16
#define EMB   32
#define VOCAB 32000
#define ROWS  (SEQ*NB)        /* 8192 */

#define BLK_M   64
#define BLK_N   512
#define NBLK_N  63                 /* ceil(32000/512) */
#define MT_PER_BLK 4               /* m-tiles per block (V staged once) */
#define NBLK_M  (ROWS/(BLK_M*MT_PER_BLK))   /* 32 */
#define NPART   (NBLK_N*4)         /* 252 partials per row */
#define VTHREADS 512
#define VS_STRIDE 520              /* padded n-stride: conflict-free frags */

#define LOG2E 1.4426950408889634f

__device__ float g_ih[ROWS*REC];
__device__ float g_hidden[ROWS*REC];
__device__ float g_part[ROWS*NPART];
__device__ float g_lse[ROWS];

/* ---- tf32 mma helpers ---- */
__device__ __forceinline__ uint32_t f2tf32(float x) {
    uint32_t r; asm("cvt.rna.tf32.f32 %0, %1;" : "=r"(r) : "f"(x)); return r;
}
__device__ __forceinline__ void mma_tf32(float* d, const uint32_t* a,
                                         uint32_t b0, uint32_t b1) {
    asm volatile(
        "mma.sync.aligned.m16n8k8.row.col.f32.tf32.tf32.f32 "
        "{%0,%1,%2,%3}, {%4,%5,%6,%7}, {%8,%9}, {%0,%1,%2,%3};\n"
        : "+f"(d[0]), "+f"(d[1]), "+f"(d[2]), "+f"(d[3])
        : "r"(a[0]), "r"(a[1]), "r"(a[2]), "r"(a[3]), "r"(b0), "r"(b1));
}

/* ---------------- kernel 0: no-op (shifts ncu capture slot) ---------- */
__global__ void k_dummy() {}

/* ---------------- kernel 1: i_h = emb[idx] @ U^T + b1 ---------------- */
__global__ void k_ih(const int* __restrict__ inp, const float* __restrict__ emb,
                     const float* __restrict__ U, const float* __restrict__ b1)
{
    int gid = blockIdx.x*blockDim.x + threadIdx.x;
    if (gid >= ROWS*REC) return;
    int row = gid >> 4;
    int r   = gid & 15;
    int idx = inp[row];
    const float4* e4 = (const float4*)(emb + (size_t)idx*EMB);
    const float4* u4 = (const float4*)(U + r*EMB);
    float acc = b1[r];
    #pragma unroll
    for (int q = 0; q < 8; q++) {
        float4 e = e4[q], u = u4[q];
        acc += e.x*u.x + e.y*u.y + e.z*u.z + e.w*u.w;
    }
    g_ih[gid] = acc;
}

/* ---------------- kernel 2: sequential recurrence (1 warp / batch) ---- */
__global__ void k_rnn(const float* __restrict__ W, const float* __restrict__ b2,
                      const float* __restrict__ h0)
{
    int b = blockIdx.x;
    int r = threadIdx.x;
    __shared__ __align__(16) float ihs[SEQ*REC];   /* 16 KB */
    __shared__ float hs[REC];

    for (int s = r; s < SEQ; s += 32) {
        const float4* src = (const float4*)(g_ih + (size_t)(s*NB + b)*REC);
        float4* dst = (float4*)(ihs + s*REC);
        dst[0]=src[0]; dst[1]=src[1]; dst[2]=src[2]; dst[3]=src[3];
    }
    float wrow[REC]; float bias = 0.f;
    if (r < REC) {
        hs[r] = h0[r];
        #pragma unroll
        for (int k = 0; k < REC; k++) wrow[k] = W[r*REC + k];
        bias = b2[r];
    }
    __syncwarp();
    for (int s = 0; s < SEQ; s++) {
        float hn = 0.f;
        if (r < REC) {
            int row = s*NB + b;
            g_hidden[row*REC + r] = hs[r];          /* pre-update h */
            float acc = ihs[s*REC + r] + bias;
            #pragma unroll
            for (int k = 0; k < REC; k++) acc += wrow[k]*hs[k];
            hn = tanhf(acc);
        }
        __syncwarp();
        if (r < REC) hs[r] = hn;
        __syncwarp();
    }
}

/* ---------------- vocab GEMM via tf32 mma.sync -----------------------
   WRITE=0: per-row sum-of-exp partials (A scaled by log2e -> exp2f).
   WRITE=1: out = logit - lse (streaming stores).
   Block: 512 thr / 16 warps; stages one 512-col V chunk, loops 4 M-tiles.
   warp w: mg = w&3 (16 rows), ng = w>>2 (128 cols).                     */
template<int WRITE>
__global__ void __launch_bounds__(VTHREADS, 2)
k_vocab(const float* __restrict__ V, float* __restrict__ out)
{
    __shared__ __align__(16) uint32_t Vs[8*VS_STRIDE > REC*VS_STRIDE ?
                                         8*VS_STRIDE : REC*VS_STRIDE]; /* 33.3KB */
    int tid  = threadIdx.x;
    int lane = tid & 31;
    int w    = tid >> 5;
    int mg   = w & 3;
    int ng   = w >> 2;
    int nBase = blockIdx.x * BLK_N;

    /* stage V^T (tf32): thread n loads one V row, scatters 16 STS */
    {
        int n  = tid;
        int gn = nBase + n;
        float4 q0, q1, q2, q3;
        if (gn < VOCAB) {
            const float4* p = (const float4*)(V + (size_t)gn*REC);
            q0 = p[0]; q1 = p[1]; q2 = p[2]; q3 = p[3];
        } else {
            q0 = q1 = q2 = q3 = make_float4(0.f,0.f,0.f,0.f);
        }
        float vv[REC] = {q0.x,q0.y,q0.z,q0.w, q1.x,q1.y,q1.z,q1.w,
                         q2.x,q2.y,q2.z,q2.w, q3.x,q3.y,q3.z,q3.w};
        #pragma unroll
        for (int k = 0; k < REC; k++)
            Vs[k*VS_STRIDE + n] = f2tf32(vv[k]);
    }
    __syncthreads();

    int g = lane >> 2, c = lane & 3;
    int nCol0 = nBase + ng*128;

    for (int mt = 0; mt < MT_PER_BLK; mt++) {
        int rowBase = (blockIdx.y*MT_PER_BLK + mt) * BLK_M;
        int r0i = rowBase + mg*16 + g;
        int r1i = r0i + 8;

        /* A fragments; pass A folds log2e so exp(logit)=exp2(d) */
        const float ascale = WRITE ? 1.f : LOG2E;
        uint32_t a[2][4];
        #pragma unroll
        for (int kh = 0; kh < 2; kh++) {
            a[kh][0] = f2tf32(ascale * g_hidden[(size_t)r0i*REC + kh*8 + c]);
            a[kh][1] = f2tf32(ascale * g_hidden[(size_t)r1i*REC + kh*8 + c]);
            a[kh][2] = f2tf32(ascale * g_hidden[(size_t)r0i*REC + kh*8 + c + 4]);
            a[kh][3] = f2tf32(ascale * g_hidden[(size_t)r1i*REC + kh*8 + c + 4]);
        }
        float lse0 = 0.f, lse1 = 0.f;
        if (WRITE) { lse0 = g_lse[r0i]; lse1 = g_lse[r1i]; }

        float sum0 = 0.f, sum1 = 0.f;

        #pragma unroll
        for (int t = 0; t < 16; t++) {
            int nc = ng*128 + t*8;
            float d[4] = {0.f, 0.f, 0.f, 0.f};
            #pragma unroll
            for (int kh = 0; kh < 2; kh++) {
                uint32_t b0 = Vs[(kh*8 + c    )*VS_STRIDE + nc + g];
                uint32_t b1 = Vs[(kh*8 + c + 4)*VS_STRIDE + nc + g];
                mma_tf32(d, a[kh], b0, b1);
            }
            int gcol = nCol0 + t*8 + 2*c;     /* pair-aligned; VOCAB%8==0 */
            if (WRITE) {
                if (gcol < VOCAB) {
                    __stcs((float2*)(out + (size_t)r0i*VOCAB + gcol),
                           make_float2(d[0]-lse0, d[1]-lse0));
                    __stcs((float2*)(out + (size_t)r1i*VOCAB + gcol),
                           make_float2(d[2]-lse1, d[3]-lse1));
                }
            } else {
                if (gcol < VOCAB) {
                    sum0 += exp2f(d[0]) + exp2f(d[1]);
                    sum1 += exp2f(d[2]) + exp2f(d[3]);
                }
            }
        }

        if (!WRITE) {
            sum0 += __shfl_xor_sync(0xffffffffu, sum0, 1);
            sum0 += __shfl_xor_sync(0xffffffffu, sum0, 2);
            sum1 += __shfl_xor_sync(0xffffffffu, sum1, 1);
            sum1 += __shfl_xor_sync(0xffffffffu, sum1, 2);
            if (c == 0) {
                int pi = blockIdx.x*4 + ng;
                g_part[(size_t)r0i*NPART + pi] = sum0;
                g_part[(size_t)r1i*NPART + pi] = sum1;
            }
        }
    }
}

/* ---------------- lse[row] = log(sum of 252 partials) ---------------- */
__global__ void k_lse()
{
    int row = blockIdx.x*blockDim.x + threadIdx.x;
    if (row >= ROWS) return;
    const float4* p = (const float4*)(g_part + (size_t)row*NPART);
    float s = 0.f;
    #pragma unroll
    for (int i = 0; i < NPART/4; i++) {
        float4 v = p[i];
        s += (v.x + v.y) + (v.z + v.w);
    }
    g_lse[row] = logf(s);
}

extern "C" void kernel_launch(void* const* d_in, const int* in_sizes, int n_in,
                              void* d_out, int out_size)
{
    const int*   inp = (const int*)d_in[0];
    const float* emb = (const float*)d_in[1];
    const float* U   = (const float*)d_in[2];
    const float* W   = (const float*)d_in[3];
    const float* V   = (const float*)d_in[4];
    const float* b1  = (const float*)d_in[5];
    const float* b2  = (const float*)d_in[6];
    const float* h0  = (const float*)d_in[7];
    float* out = (float*)d_out;

    k_dummy<<<1, 32>>>();      /* shifts ncu capture slot onto k_vocab<0> */
    k_ih<<<(ROWS*REC + 255)/256, 256>>>(inp, emb, U, b1);
    k_rnn<<<NB, 32>>>(W, b2, h0);
    k_vocab<0><<<dim3(NBLK_N, NBLK_M), VTHREADS>>>(V, nullptr);
    k_lse<<<(ROWS + 255)/256, 256>>>();
    k_vocab<1><<<dim3(NBLK_N, NBLK_M), VTHREADS>>>(V, out);
}